// round 3
// baseline (speedup 1.0000x reference)
#include <cuda_runtime.h>

constexpr int NB = 4, NT = 256, NH = 512, NE = 512, NV = 32000;
constexpr int BT = NB * NT;                 // 1024
constexpr int RNN_BLOCKS = 32, RNN_JCOL = 16;

// ---------------- device scratch (no allocations allowed) ----------------
__device__ float g_emb   [BT * NE];
__device__ float g_X     [BT * NH];
__device__ float g_rnn   [BT * NH];
__device__ float g_penc  [BT * NH];
__device__ float g_pdec  [BT * NH];
__device__ float g_scores[NB * NT * NT];
__device__ float g_comb  [BT * 2 * NH];
__device__ unsigned g_bar;

// ---------------- FFMA-only math (keep off the MUFU pipe) ----------------
__device__ __forceinline__ float fexp(float x) {
    float y = x * 1.4426950408889634f;
    y = fminf(fmaxf(y, -125.f), 125.f);
    float fk = y + 12582912.f;                  // round-to-nearest via magic add
    int   k  = __float_as_int(fk) - 0x4B400000;
    float f  = y - (fk - 12582912.f);           // f in [-0.5, 0.5]
    float p  = 1.54035304e-4f;
    p = fmaf(p, f, 1.33335581e-3f);
    p = fmaf(p, f, 9.61812911e-3f);
    p = fmaf(p, f, 5.55041087e-2f);
    p = fmaf(p, f, 2.40226507e-1f);
    p = fmaf(p, f, 6.93147181e-1f);
    p = fmaf(p, f, 1.0f);
    return p * __int_as_float((k + 127) << 23);
}
__device__ __forceinline__ float frcp_pos(float d) {
    float r = __int_as_float(0x7EF311C3 - __float_as_int(d));
    r = r * (2.0f - d * r);
    r = r * (2.0f - d * r);
    r = r * (2.0f - d * r);
    return r;
}
__device__ __forceinline__ float ftanh(float x) {
    float z = fminf(fmaxf(x, -10.f), 10.f);
    float t = fexp(2.0f * z);
    return 1.0f - 2.0f * frcp_pos(t + 1.0f);
}

// ---------------- kernels ----------------
__global__ void reset_kernel() { g_bar = 0u; }

__global__ __launch_bounds__(256) void gather_kernel(const int* __restrict__ x,
                                                     const float* __restrict__ embed) {
    int idx = blockIdx.x * 256 + threadIdx.x;     // over BT*NE/4
    int m = idx >> 7, c = idx & 127;              // NE/4 = 128
    int tok = x[m];
    reinterpret_cast<float4*>(g_emb)[idx] =
        reinterpret_cast<const float4*>(embed)[(size_t)tok * (NE / 4) + c];
}

// Persistent RNN scan: 32 blocks, each owns 16 output columns.
__global__ __launch_bounds__(256) void rnn_kernel(const float* __restrict__ Whh,
                                                  const float* __restrict__ h0) {
    __shared__ float  Ws[NH * RNN_JCOL];     // 32 KB
    __shared__ float4 hs[NH];                // 8 KB (h transposed: hs[i] = batches 0..3)
    __shared__ float  red[16 * 64];          // 4 KB

    const int tid = threadIdx.x;
    const int j0  = blockIdx.x * RNN_JCOL;
    for (int idx = tid; idx < NH * RNN_JCOL; idx += 256) {
        int i = idx >> 4, jl = idx & 15;
        Ws[idx] = Whh[i * NH + j0 + jl];
    }
    const int ic = tid >> 4;      // 0..15, each handles 32 rows
    const int jl = tid & 15;
    const int i0 = ic << 5;

    for (int s = 0; s < NT; ++s) {
        if (s > 0 && tid == 0) {
            unsigned target = (unsigned)(RNN_BLOCKS * s);
            while (*((volatile unsigned*)&g_bar) < target) {}
        }
        __syncthreads();
        #pragma unroll
        for (int q = 0; q < 8; ++q) {
            int idx = (q << 8) + tid;
            int b = idx >> 9, i = idx & (NH - 1);
            float v = (s == 0) ? h0[idx]
                               : g_rnn[(size_t)(((b << 8) + (s - 1))) * NH + i];
            reinterpret_cast<float*>(hs)[(i << 2) + b] = v;
        }
        __syncthreads();

        float4 acc = make_float4(0.f, 0.f, 0.f, 0.f);
        #pragma unroll
        for (int r = 0; r < 32; ++r) {
            int i = i0 + r;
            float  w  = Ws[(i << 4) + jl];
            float4 h4 = hs[i];
            acc.x = fmaf(w, h4.x, acc.x);
            acc.y = fmaf(w, h4.y, acc.y);
            acc.z = fmaf(w, h4.z, acc.z);
            acc.w = fmaf(w, h4.w, acc.w);
        }
        *reinterpret_cast<float4*>(&red[(ic << 6) + (jl << 2)]) = acc;
        __syncthreads();

        if (tid < 64) {
            int jj = tid >> 2, b = tid & 3;
            float sum = 0.f;
            #pragma unroll
            for (int c = 0; c < 16; ++c) sum += red[(c << 6) + (jj << 2) + b];
            sum += g_X[(size_t)((b << 8) + s) * NH + j0 + jj];
            g_rnn[(size_t)((b << 8) + s) * NH + j0 + jj] = ftanh(sum);
        }
        __threadfence();
        __syncthreads();
        if (tid == 0) atomicAdd(&g_bar, 1u);
    }
}

// Generic fp32 tiled GEMM: C[M,N] = A[M,K] @ B[K,N] (+bias1) (+bias2), row-major.
template<int BM, int BN, int BK, int TM, int TN>
__global__ __launch_bounds__((BM / TM) * (BN / TN))
void gemm_kernel(const float* __restrict__ A, const float* __restrict__ B,
                 float* __restrict__ C, int M, int N, int K,
                 const float* __restrict__ bias1, const float* __restrict__ bias2) {
    __shared__ float As[2][BK][BM];
    __shared__ float Bs[2][BK][BN];
    const int tid  = threadIdx.x;
    const int arow = tid / (BK / 4);
    const int acol = (tid % (BK / 4)) * 4;
    const int brow = tid / (BN / 4);
    const int bcol = (tid % (BN / 4)) * 4;
    const float* Ap = A + (size_t)(blockIdx.y * BM + arow) * K + acol;
    const float* Bp = B + (size_t)brow * N + blockIdx.x * BN + bcol;
    const int tx = tid % (BN / TN);
    const int ty = tid / (BN / TN);

    float acc[TM][TN];
    #pragma unroll
    for (int i = 0; i < TM; ++i)
        #pragma unroll
        for (int j = 0; j < TN; ++j) acc[i][j] = 0.f;

    float4 ra = *reinterpret_cast<const float4*>(Ap);
    float4 rb = *reinterpret_cast<const float4*>(Bp);
    As[0][acol + 0][arow] = ra.x; As[0][acol + 1][arow] = ra.y;
    As[0][acol + 2][arow] = ra.z; As[0][acol + 3][arow] = ra.w;
    *reinterpret_cast<float4*>(&Bs[0][brow][bcol]) = rb;
    __syncthreads();

    const int KT = K / BK;
    for (int kt = 0; kt < KT; ++kt) {
        const int cur = kt & 1;
        if (kt + 1 < KT) {
            ra = *reinterpret_cast<const float4*>(Ap + (size_t)(kt + 1) * BK);
            rb = *reinterpret_cast<const float4*>(Bp + (size_t)(kt + 1) * BK * N);
        }
        #pragma unroll
        for (int k = 0; k < BK; ++k) {
            float a[TM], b[TN];
            #pragma unroll
            for (int u = 0; u < TM; u += 4) {
                float4 t = *reinterpret_cast<const float4*>(&As[cur][k][ty * TM + u]);
                a[u] = t.x; a[u + 1] = t.y; a[u + 2] = t.z; a[u + 3] = t.w;
            }
            #pragma unroll
            for (int u = 0; u < TN; u += 4) {
                float4 t = *reinterpret_cast<const float4*>(&Bs[cur][k][tx * TN + u]);
                b[u] = t.x; b[u + 1] = t.y; b[u + 2] = t.z; b[u + 3] = t.w;
            }
            #pragma unroll
            for (int i = 0; i < TM; ++i)
                #pragma unroll
                for (int j = 0; j < TN; ++j)
                    acc[i][j] = fmaf(a[i], b[j], acc[i][j]);
        }
        if (kt + 1 < KT) {
            const int nxt = cur ^ 1;
            As[nxt][acol + 0][arow] = ra.x; As[nxt][acol + 1][arow] = ra.y;
            As[nxt][acol + 2][arow] = ra.z; As[nxt][acol + 3][arow] = ra.w;
            *reinterpret_cast<float4*>(&Bs[nxt][brow][bcol]) = rb;
        }
        __syncthreads();
    }

    #pragma unroll
    for (int i = 0; i < TM; ++i) {
        size_t row = (size_t)blockIdx.y * BM + ty * TM + i;
        #pragma unroll
        for (int j = 0; j < TN; j += 4) {
            int col = blockIdx.x * BN + tx * TN + j;
            float4 v = make_float4(acc[i][j], acc[i][j + 1], acc[i][j + 2], acc[i][j + 3]);
            if (bias1) { v.x += bias1[col]; v.y += bias1[col+1]; v.z += bias1[col+2]; v.w += bias1[col+3]; }
            if (bias2) { v.x += bias2[col]; v.y += bias2[col+1]; v.z += bias2[col+2]; v.w += bias2[col+3]; }
            *reinterpret_cast<float4*>(&C[row * N + col]) = v;
        }
    }
}

// scores[b,d,e] = sum_h tanh(penc[b,e,h]+pdec[b,d,h]) * v[h], e <= d.  Warp per e.
__global__ __launch_bounds__(256) void scores_kernel(const float* __restrict__ attn_v) {
    __shared__ float pdec_s[NH];
    __shared__ float v_s[NH];
    const int d = blockIdx.x, b = blockIdx.y;
    const int tid = threadIdx.x, lane = tid & 31, wid = tid >> 5;

    for (int i = tid; i < NH; i += 256) {
        pdec_s[i] = g_pdec[(size_t)((b << 8) + d) * NH + i];
        v_s[i]    = attn_v[i];
    }
    __syncthreads();

    for (int e0 = 0; e0 <= d; e0 += 8) {
        int e = e0 + wid;
        if (e <= d) {
            const float* pe = g_penc + (size_t)((b << 8) + e) * NH;
            float acc = 0.f;
            #pragma unroll
            for (int q = 0; q < 4; ++q) {
                int h = (lane << 2) + (q << 7);
                float4 p = *reinterpret_cast<const float4*>(pe + h);
                float4 pd = *reinterpret_cast<const float4*>(&pdec_s[h]);
                float4 vv = *reinterpret_cast<const float4*>(&v_s[h]);
                acc = fmaf(ftanh(p.x + pd.x), vv.x, acc);
                acc = fmaf(ftanh(p.y + pd.y), vv.y, acc);
                acc = fmaf(ftanh(p.z + pd.z), vv.z, acc);
                acc = fmaf(ftanh(p.w + pd.w), vv.w, acc);
            }
            #pragma unroll
            for (int o = 16; o; o >>= 1) acc += __shfl_xor_sync(0xFFFFFFFFu, acc, o);
            if (lane == 0) g_scores[(size_t)((b << 8) + d) * NT + e] = acc;
        }
    }
}

// softmax over e<=d, context = sum_e w_e * rnn[b,e,:], write combined = [rnn_d, ctx].
__global__ __launch_bounds__(128) void softmax_ctx_kernel() {
    __shared__ float w_s[NT];
    __shared__ float sm[4];
    const int d = blockIdx.x, b = blockIdx.y, tid = threadIdx.x;
    const int n = d + 1;
    const float* srow = g_scores + (size_t)((b << 8) + d) * NT;

    float s0 = (tid < n) ? srow[tid] : -1e30f;
    float s1 = (tid + 128 < n) ? srow[tid + 128] : -1e30f;
    float m = fmaxf(s0, s1);
    #pragma unroll
    for (int o = 16; o; o >>= 1) m = fmaxf(m, __shfl_xor_sync(0xFFFFFFFFu, m, o));
    if ((tid & 31) == 0) sm[tid >> 5] = m;
    __syncthreads();
    m = fmaxf(fmaxf(sm[0], sm[1]), fmaxf(sm[2], sm[3]));
    __syncthreads();

    float e0 = (tid < n) ? fexp(s0 - m) : 0.f;
    float e1 = (tid + 128 < n) ? fexp(s1 - m) : 0.f;
    float sum = e0 + e1;
    #pragma unroll
    for (int o = 16; o; o >>= 1) sum += __shfl_xor_sync(0xFFFFFFFFu, sum, o);
    if ((tid & 31) == 0) sm[tid >> 5] = sum;
    __syncthreads();
    sum = sm[0] + sm[1] + sm[2] + sm[3];
    float inv = frcp_pos(sum);
    if (tid < n) w_s[tid] = e0 * inv;
    if (tid + 128 < n) w_s[tid + 128] = e1 * inv;
    __syncthreads();

    float4 acc = make_float4(0.f, 0.f, 0.f, 0.f);
    const float* rb = g_rnn + (size_t)(b << 8) * NH + (tid << 2);
    for (int e = 0; e < n; ++e) {
        float w = w_s[e];
        float4 r = *reinterpret_cast<const float4*>(rb + (size_t)e * NH);
        acc.x = fmaf(w, r.x, acc.x);
        acc.y = fmaf(w, r.y, acc.y);
        acc.z = fmaf(w, r.z, acc.z);
        acc.w = fmaf(w, r.w, acc.w);
    }
    float4 own = *reinterpret_cast<const float4*>(
        g_rnn + (size_t)((b << 8) + d) * NH + (tid << 2));
    float* cm = g_comb + (size_t)((b << 8) + d) * (2 * NH);
    *reinterpret_cast<float4*>(cm + (tid << 2)) = own;
    *reinterpret_cast<float4*>(cm + NH + (tid << 2)) = acc;
}

__global__ void hlast_kernel(float* __restrict__ out) {
    int idx = blockIdx.x * 512 + threadIdx.x;     // 0..2047
    int b = idx >> 9, i = idx & 511;
    out[idx] = g_rnn[(size_t)((b << 8) + (NT - 1)) * NH + i];
}

// ---------------- launch ----------------
extern "C" void kernel_launch(void* const* d_in, const int* in_sizes, int n_in,
                              void* d_out, int out_size) {
    const int*   x      = (const int*)  d_in[0];
    const float* embed  = (const float*)d_in[1];
    const float* W_ih   = (const float*)d_in[2];
    const float* W_hh   = (const float*)d_in[3];
    const float* b_ih   = (const float*)d_in[4];
    const float* b_hh   = (const float*)d_in[5];
    const float* attn_W = (const float*)d_in[6];
    const float* attn_U = (const float*)d_in[7];
    const float* attn_v = (const float*)d_in[8];
    const float* fc_W   = (const float*)d_in[9];
    const float* fc_b   = (const float*)d_in[10];
    const float* h0     = (const float*)d_in[11];
    float* out = (float*)d_out;

    float *emb, *X, *rnn, *penc, *pdec, *comb;
    cudaGetSymbolAddress((void**)&emb,  g_emb);
    cudaGetSymbolAddress((void**)&X,    g_X);
    cudaGetSymbolAddress((void**)&rnn,  g_rnn);
    cudaGetSymbolAddress((void**)&penc, g_penc);
    cudaGetSymbolAddress((void**)&pdec, g_pdec);
    cudaGetSymbolAddress((void**)&comb, g_comb);

    reset_kernel<<<1, 1>>>();
    gather_kernel<<<BT * NE / 4 / 256, 256>>>(x, embed);
    gemm_kernel<64, 64, 16, 4, 4><<<dim3(NH / 64, BT / 64), 256>>>(
        emb, W_ih, X, BT, NH, NE, b_ih, b_hh);
    rnn_kernel<<<RNN_BLOCKS, 256>>>(W_hh, h0);
    gemm_kernel<64, 64, 16, 4, 4><<<dim3(NH / 64, BT / 64), 256>>>(
        rnn, attn_W, penc, BT, NH, NH, nullptr, nullptr);
    gemm_kernel<64, 64, 16, 4, 4><<<dim3(NH / 64, BT / 64), 256>>>(
        rnn, attn_U, pdec, BT, NH, NH, nullptr, nullptr);
    scores_kernel<<<dim3(NT, NB), 256>>>(attn_v);
    softmax_ctx_kernel<<<dim3(NT, NB), 128>>>();
    gemm_kernel<128, 128, 8, 8, 8><<<dim3(NV / 128, BT / 128), 256>>>(
        comb, fc_W, out, BT, NV, 2 * NH, fc_b, nullptr);
    hlast_kernel<<<4, 512>>>(out + (size_t)BT * NV);
}

// round 4
// speedup vs baseline: 1.0046x; 1.0046x over previous
#include <cuda_runtime.h>

constexpr int NB = 4, NT = 256, NH = 512, NE = 512, NV = 32000;
constexpr int BT = NB * NT;                 // 1024
constexpr int RNN_BLOCKS = 32, RNN_JCOL = 16;

// ---------------- device scratch (no allocations allowed) ----------------
__device__ float g_emb   [BT * NE];
__device__ float g_X     [BT * NH];
__device__ float g_rnn   [BT * NH];
__device__ float g_penc  [BT * NH];
__device__ float g_pdec  [BT * NH];
__device__ float g_scores[NB * NT * NT];
__device__ float g_comb  [BT * 2 * NH];
__device__ unsigned g_bar;

// ---------------- FFMA-only math (keep off the MUFU pipe) ----------------
__device__ __forceinline__ float fexp(float x) {
    float y = x * 1.4426950408889634f;
    y = fminf(fmaxf(y, -125.f), 125.f);
    float fk = y + 12582912.f;                  // round-to-nearest via magic add
    int   k  = __float_as_int(fk) - 0x4B400000;
    float f  = y - (fk - 12582912.f);           // f in [-0.5, 0.5]
    float p  = 1.54035304e-4f;
    p = fmaf(p, f, 1.33335581e-3f);
    p = fmaf(p, f, 9.61812911e-3f);
    p = fmaf(p, f, 5.55041087e-2f);
    p = fmaf(p, f, 2.40226507e-1f);
    p = fmaf(p, f, 6.93147181e-1f);
    p = fmaf(p, f, 1.0f);
    return p * __int_as_float((k + 127) << 23);
}
__device__ __forceinline__ float frcp_pos(float d) {
    float r = __int_as_float(0x7EF311C3 - __float_as_int(d));
    r = r * (2.0f - d * r);
    r = r * (2.0f - d * r);
    r = r * (2.0f - d * r);
    return r;
}
__device__ __forceinline__ float ftanh(float x) {
    float z = fminf(fmaxf(x, -10.f), 10.f);
    float t = fexp(2.0f * z);
    return 1.0f - 2.0f * frcp_pos(t + 1.0f);
}

// ---------------- kernels ----------------
__global__ void reset_kernel() { g_bar = 0u; }

__global__ __launch_bounds__(256) void gather_kernel(const int* __restrict__ x,
                                                     const float* __restrict__ embed) {
    int idx = blockIdx.x * 256 + threadIdx.x;     // over BT*NE/4
    int m = idx >> 7, c = idx & 127;              // NE/4 = 128
    int tok = x[m];
    reinterpret_cast<float4*>(g_emb)[idx] =
        reinterpret_cast<const float4*>(embed)[(size_t)tok * (NE / 4) + c];
}

// Persistent RNN scan: 32 blocks, each owns 16 output columns.
__global__ __launch_bounds__(256) void rnn_kernel(const float* __restrict__ Whh,
                                                  const float* __restrict__ h0) {
    __shared__ float  Ws[NH * RNN_JCOL];     // 32 KB
    __shared__ float4 hs[NH];                // 8 KB (h transposed: hs[i] = batches 0..3)
    __shared__ float  red[16 * 64];          // 4 KB

    const int tid = threadIdx.x;
    const int j0  = blockIdx.x * RNN_JCOL;
    for (int idx = tid; idx < NH * RNN_JCOL; idx += 256) {
        int i = idx >> 4, jl = idx & 15;
        Ws[idx] = Whh[i * NH + j0 + jl];
    }
    const int ic = tid >> 4;      // 0..15, each handles 32 rows
    const int jl = tid & 15;
    const int i0 = ic << 5;

    for (int s = 0; s < NT; ++s) {
        if (s > 0 && tid == 0) {
            unsigned target = (unsigned)(RNN_BLOCKS * s);
            while (*((volatile unsigned*)&g_bar) < target) {}
        }
        __syncthreads();
        #pragma unroll
        for (int q = 0; q < 8; ++q) {
            int idx = (q << 8) + tid;
            int b = idx >> 9, i = idx & (NH - 1);
            float v = (s == 0) ? h0[idx]
                               : g_rnn[(size_t)(((b << 8) + (s - 1))) * NH + i];
            reinterpret_cast<float*>(hs)[(i << 2) + b] = v;
        }
        __syncthreads();

        float4 acc = make_float4(0.f, 0.f, 0.f, 0.f);
        #pragma unroll
        for (int r = 0; r < 32; ++r) {
            int i = i0 + r;
            float  w  = Ws[(i << 4) + jl];
            float4 h4 = hs[i];
            acc.x = fmaf(w, h4.x, acc.x);
            acc.y = fmaf(w, h4.y, acc.y);
            acc.z = fmaf(w, h4.z, acc.z);
            acc.w = fmaf(w, h4.w, acc.w);
        }
        *reinterpret_cast<float4*>(&red[(ic << 6) + (jl << 2)]) = acc;
        __syncthreads();

        if (tid < 64) {
            int jj = tid >> 2, b = tid & 3;
            float sum = 0.f;
            #pragma unroll
            for (int c = 0; c < 16; ++c) sum += red[(c << 6) + (jj << 2) + b];
            sum += g_X[(size_t)((b << 8) + s) * NH + j0 + jj];
            g_rnn[(size_t)((b << 8) + s) * NH + j0 + jj] = ftanh(sum);
        }
        __threadfence();
        __syncthreads();
        if (tid == 0) atomicAdd(&g_bar, 1u);
    }
}

// Generic fp32 tiled GEMM: C[M,N] = A[M,K] @ B[K,N] (+bias1) (+bias2), row-major.
template<int BM, int BN, int BK, int TM, int TN>
__global__ __launch_bounds__((BM / TM) * (BN / TN))
void gemm_kernel(const float* __restrict__ A, const float* __restrict__ B,
                 float* __restrict__ C, int M, int N, int K,
                 const float* __restrict__ bias1, const float* __restrict__ bias2) {
    __shared__ float As[2][BK][BM];
    __shared__ float Bs[2][BK][BN];
    const int tid  = threadIdx.x;
    const int arow = tid / (BK / 4);
    const int acol = (tid % (BK / 4)) * 4;
    const int brow = tid / (BN / 4);
    const int bcol = (tid % (BN / 4)) * 4;
    const float* Ap = A + (size_t)(blockIdx.y * BM + arow) * K + acol;
    const float* Bp = B + (size_t)brow * N + blockIdx.x * BN + bcol;
    const int tx = tid % (BN / TN);
    const int ty = tid / (BN / TN);

    float acc[TM][TN];
    #pragma unroll
    for (int i = 0; i < TM; ++i)
        #pragma unroll
        for (int j = 0; j < TN; ++j) acc[i][j] = 0.f;

    float4 ra = *reinterpret_cast<const float4*>(Ap);
    float4 rb = *reinterpret_cast<const float4*>(Bp);
    As[0][acol + 0][arow] = ra.x; As[0][acol + 1][arow] = ra.y;
    As[0][acol + 2][arow] = ra.z; As[0][acol + 3][arow] = ra.w;
    *reinterpret_cast<float4*>(&Bs[0][brow][bcol]) = rb;
    __syncthreads();

    const int KT = K / BK;
    for (int kt = 0; kt < KT; ++kt) {
        const int cur = kt & 1;
        if (kt + 1 < KT) {
            ra = *reinterpret_cast<const float4*>(Ap + (size_t)(kt + 1) * BK);
            rb = *reinterpret_cast<const float4*>(Bp + (size_t)(kt + 1) * BK * N);
        }
        #pragma unroll
        for (int k = 0; k < BK; ++k) {
            float a[TM], b[TN];
            #pragma unroll
            for (int u = 0; u < TM; u += 4) {
                float4 t = *reinterpret_cast<const float4*>(&As[cur][k][ty * TM + u]);
                a[u] = t.x; a[u + 1] = t.y; a[u + 2] = t.z; a[u + 3] = t.w;
            }
            #pragma unroll
            for (int u = 0; u < TN; u += 4) {
                float4 t = *reinterpret_cast<const float4*>(&Bs[cur][k][tx * TN + u]);
                b[u] = t.x; b[u + 1] = t.y; b[u + 2] = t.z; b[u + 3] = t.w;
            }
            #pragma unroll
            for (int i = 0; i < TM; ++i)
                #pragma unroll
                for (int j = 0; j < TN; ++j)
                    acc[i][j] = fmaf(a[i], b[j], acc[i][j]);
        }
        if (kt + 1 < KT) {
            const int nxt = cur ^ 1;
            As[nxt][acol + 0][arow] = ra.x; As[nxt][acol + 1][arow] = ra.y;
            As[nxt][acol + 2][arow] = ra.z; As[nxt][acol + 3][arow] = ra.w;
            *reinterpret_cast<float4*>(&Bs[nxt][brow][bcol]) = rb;
        }
        __syncthreads();
    }

    #pragma unroll
    for (int i = 0; i < TM; ++i) {
        size_t row = (size_t)blockIdx.y * BM + ty * TM + i;
        #pragma unroll
        for (int j = 0; j < TN; j += 4) {
            int col = blockIdx.x * BN + tx * TN + j;
            float4 v = make_float4(acc[i][j], acc[i][j + 1], acc[i][j + 2], acc[i][j + 3]);
            if (bias1) { v.x += bias1[col]; v.y += bias1[col+1]; v.z += bias1[col+2]; v.w += bias1[col+3]; }
            if (bias2) { v.x += bias2[col]; v.y += bias2[col+1]; v.z += bias2[col+2]; v.w += bias2[col+3]; }
            *reinterpret_cast<float4*>(&C[row * N + col]) = v;
        }
    }
}

// scores[b,d,e] = sum_h tanh(penc[b,e,h]+pdec[b,d,h]) * v[h], e <= d.  Warp per e.
__global__ __launch_bounds__(256) void scores_kernel(const float* __restrict__ attn_v) {
    __shared__ float pdec_s[NH];
    __shared__ float v_s[NH];
    const int d = blockIdx.x, b = blockIdx.y;
    const int tid = threadIdx.x, lane = tid & 31, wid = tid >> 5;

    for (int i = tid; i < NH; i += 256) {
        pdec_s[i] = g_pdec[(size_t)((b << 8) + d) * NH + i];
        v_s[i]    = attn_v[i];
    }
    __syncthreads();

    for (int e0 = 0; e0 <= d; e0 += 8) {
        int e = e0 + wid;
        if (e <= d) {
            const float* pe = g_penc + (size_t)((b << 8) + e) * NH;
            float acc = 0.f;
            #pragma unroll
            for (int q = 0; q < 4; ++q) {
                int h = (lane << 2) + (q << 7);
                float4 p = *reinterpret_cast<const float4*>(pe + h);
                float4 pd = *reinterpret_cast<const float4*>(&pdec_s[h]);
                float4 vv = *reinterpret_cast<const float4*>(&v_s[h]);
                acc = fmaf(ftanh(p.x + pd.x), vv.x, acc);
                acc = fmaf(ftanh(p.y + pd.y), vv.y, acc);
                acc = fmaf(ftanh(p.z + pd.z), vv.z, acc);
                acc = fmaf(ftanh(p.w + pd.w), vv.w, acc);
            }
            #pragma unroll
            for (int o = 16; o; o >>= 1) acc += __shfl_xor_sync(0xFFFFFFFFu, acc, o);
            if (lane == 0) g_scores[(size_t)((b << 8) + d) * NT + e] = acc;
        }
    }
}

// softmax over e<=d, context = sum_e w_e * rnn[b,e,:], write combined = [rnn_d, ctx].
__global__ __launch_bounds__(128) void softmax_ctx_kernel() {
    __shared__ float w_s[NT];
    __shared__ float sm[4];
    const int d = blockIdx.x, b = blockIdx.y, tid = threadIdx.x;
    const int n = d + 1;
    const float* srow = g_scores + (size_t)((b << 8) + d) * NT;

    float s0 = (tid < n) ? srow[tid] : -1e30f;
    float s1 = (tid + 128 < n) ? srow[tid + 128] : -1e30f;
    float m = fmaxf(s0, s1);
    #pragma unroll
    for (int o = 16; o; o >>= 1) m = fmaxf(m, __shfl_xor_sync(0xFFFFFFFFu, m, o));
    if ((tid & 31) == 0) sm[tid >> 5] = m;
    __syncthreads();
    m = fmaxf(fmaxf(sm[0], sm[1]), fmaxf(sm[2], sm[3]));
    __syncthreads();

    float e0 = (tid < n) ? fexp(s0 - m) : 0.f;
    float e1 = (tid + 128 < n) ? fexp(s1 - m) : 0.f;
    float sum = e0 + e1;
    #pragma unroll
    for (int o = 16; o; o >>= 1) sum += __shfl_xor_sync(0xFFFFFFFFu, sum, o);
    if ((tid & 31) == 0) sm[tid >> 5] = sum;
    __syncthreads();
    sum = sm[0] + sm[1] + sm[2] + sm[3];
    float inv = frcp_pos(sum);
    if (tid < n) w_s[tid] = e0 * inv;
    if (tid + 128 < n) w_s[tid + 128] = e1 * inv;
    __syncthreads();

    float4 acc = make_float4(0.f, 0.f, 0.f, 0.f);
    const float* rb = g_rnn + (size_t)(b << 8) * NH + (tid << 2);
    for (int e = 0; e < n; ++e) {
        float w = w_s[e];
        float4 r = *reinterpret_cast<const float4*>(rb + (size_t)e * NH);
        acc.x = fmaf(w, r.x, acc.x);
        acc.y = fmaf(w, r.y, acc.y);
        acc.z = fmaf(w, r.z, acc.z);
        acc.w = fmaf(w, r.w, acc.w);
    }
    float4 own = *reinterpret_cast<const float4*>(
        g_rnn + (size_t)((b << 8) + d) * NH + (tid << 2));
    float* cm = g_comb + (size_t)((b << 8) + d) * (2 * NH);
    *reinterpret_cast<float4*>(cm + (tid << 2)) = own;
    *reinterpret_cast<float4*>(cm + NH + (tid << 2)) = acc;
}

__global__ void hlast_kernel(float* __restrict__ out) {
    int idx = blockIdx.x * 512 + threadIdx.x;     // 0..2047
    int b = idx >> 9, i = idx & 511;
    out[idx] = g_rnn[(size_t)((b << 8) + (NT - 1)) * NH + i];
}

// ---------------- launch ----------------
extern "C" void kernel_launch(void* const* d_in, const int* in_sizes, int n_in,
                              void* d_out, int out_size) {
    const int*   x      = (const int*)  d_in[0];
    const float* embed  = (const float*)d_in[1];
    const float* W_ih   = (const float*)d_in[2];
    const float* W_hh   = (const float*)d_in[3];
    const float* b_ih   = (const float*)d_in[4];
    const float* b_hh   = (const float*)d_in[5];
    const float* attn_W = (const float*)d_in[6];
    const float* attn_U = (const float*)d_in[7];
    const float* attn_v = (const float*)d_in[8];
    const float* fc_W   = (const float*)d_in[9];
    const float* fc_b   = (const float*)d_in[10];
    const float* h0     = (const float*)d_in[11];
    float* out = (float*)d_out;

    float *emb, *X, *rnn, *penc, *pdec, *comb;
    cudaGetSymbolAddress((void**)&emb,  g_emb);
    cudaGetSymbolAddress((void**)&X,    g_X);
    cudaGetSymbolAddress((void**)&rnn,  g_rnn);
    cudaGetSymbolAddress((void**)&penc, g_penc);
    cudaGetSymbolAddress((void**)&pdec, g_pdec);
    cudaGetSymbolAddress((void**)&comb, g_comb);

    reset_kernel<<<1, 1>>>();
    gather_kernel<<<BT * NE / 4 / 256, 256>>>(x, embed);
    gemm_kernel<64, 64, 16, 4, 4><<<dim3(NH / 64, BT / 64), 256>>>(
        emb, W_ih, X, BT, NH, NE, b_ih, b_hh);
    rnn_kernel<<<RNN_BLOCKS, 256>>>(W_hh, h0);
    gemm_kernel<64, 64, 16, 4, 4><<<dim3(NH / 64, BT / 64), 256>>>(
        rnn, attn_W, penc, BT, NH, NH, nullptr, nullptr);
    gemm_kernel<64, 64, 16, 4, 4><<<dim3(NH / 64, BT / 64), 256>>>(
        rnn, attn_U, pdec, BT, NH, NH, nullptr, nullptr);
    scores_kernel<<<dim3(NT, NB), 256>>>(attn_v);
    softmax_ctx_kernel<<<dim3(NT, NB), 128>>>();
    gemm_kernel<128, 128, 8, 8, 8><<<dim3(NV / 128, BT / 128), 256>>>(
        comb, fc_W, out, BT, NV, 2 * NH, fc_b, nullptr);
    hlast_kernel<<<4, 512>>>(out + (size_t)BT * NV);
}

// round 5
// speedup vs baseline: 1.0051x; 1.0005x over previous
#include <cuda_runtime.h>

constexpr int NB = 4, NT = 256, NH = 512, NE = 512, NV = 32000;
constexpr int BT = NB * NT;                 // 1024
constexpr int RNN_BLOCKS = 32, RNN_JCOL = 16;

// ---------------- device scratch (no allocations allowed) ----------------
__device__ float g_emb   [BT * NE];
__device__ float g_X     [BT * NH];
__device__ float g_rnn   [BT * NH];
__device__ float g_penc  [BT * NH];
__device__ float g_pdec  [BT * NH];
__device__ float g_scores[NB * NT * NT];
__device__ float g_comb  [BT * 2 * NH];
__device__ unsigned g_bar;

// ---------------- FFMA-only math (keep off the MUFU pipe) ----------------
__device__ __forceinline__ float fexp(float x) {
    float y = x * 1.4426950408889634f;
    y = fminf(fmaxf(y, -125.f), 125.f);
    float fk = y + 12582912.f;                  // round-to-nearest via magic add
    int   k  = __float_as_int(fk) - 0x4B400000;
    float f  = y - (fk - 12582912.f);           // f in [-0.5, 0.5]
    float p  = 1.54035304e-4f;
    p = fmaf(p, f, 1.33335581e-3f);
    p = fmaf(p, f, 9.61812911e-3f);
    p = fmaf(p, f, 5.55041087e-2f);
    p = fmaf(p, f, 2.40226507e-1f);
    p = fmaf(p, f, 6.93147181e-1f);
    p = fmaf(p, f, 1.0f);
    return p * __int_as_float((k + 127) << 23);
}
__device__ __forceinline__ float frcp_pos(float d) {
    float r = __int_as_float(0x7EF311C3 - __float_as_int(d));
    r = r * (2.0f - d * r);
    r = r * (2.0f - d * r);
    r = r * (2.0f - d * r);
    return r;
}
__device__ __forceinline__ float ftanh(float x) {
    float z = fminf(fmaxf(x, -10.f), 10.f);
    float t = fexp(2.0f * z);
    return 1.0f - 2.0f * frcp_pos(t + 1.0f);
}

// ---------------- kernels ----------------
__global__ void reset_kernel() { g_bar = 0u; }

__global__ __launch_bounds__(256) void gather_kernel(const int* __restrict__ x,
                                                     const float* __restrict__ embed) {
    int idx = blockIdx.x * 256 + threadIdx.x;     // over BT*NE/4
    int m = idx >> 7, c = idx & 127;              // NE/4 = 128
    int tok = x[m];
    reinterpret_cast<float4*>(g_emb)[idx] =
        reinterpret_cast<const float4*>(embed)[(size_t)tok * (NE / 4) + c];
}

// Persistent RNN scan: 32 blocks, each owns 16 output columns.
__global__ __launch_bounds__(256) void rnn_kernel(const float* __restrict__ Whh,
                                                  const float* __restrict__ h0) {
    __shared__ float  Ws[NH * RNN_JCOL];     // 32 KB
    __shared__ float4 hs[NH];                // 8 KB (h transposed: hs[i] = batches 0..3)
    __shared__ float  red[16 * 64];          // 4 KB

    const int tid = threadIdx.x;
    const int j0  = blockIdx.x * RNN_JCOL;
    for (int idx = tid; idx < NH * RNN_JCOL; idx += 256) {
        int i = idx >> 4, jl = idx & 15;
        Ws[idx] = Whh[i * NH + j0 + jl];
    }
    const int ic = tid >> 4;      // 0..15, each handles 32 rows
    const int jl = tid & 15;
    const int i0 = ic << 5;

    for (int s = 0; s < NT; ++s) {
        if (s > 0 && tid == 0) {
            unsigned target = (unsigned)(RNN_BLOCKS * s);
            while (*((volatile unsigned*)&g_bar) < target) {}
        }
        __syncthreads();
        #pragma unroll
        for (int q = 0; q < 8; ++q) {
            int idx = (q << 8) + tid;
            int b = idx >> 9, i = idx & (NH - 1);
            float v = (s == 0) ? h0[idx]
                               : g_rnn[(size_t)(((b << 8) + (s - 1))) * NH + i];
            reinterpret_cast<float*>(hs)[(i << 2) + b] = v;
        }
        __syncthreads();

        float4 acc = make_float4(0.f, 0.f, 0.f, 0.f);
        #pragma unroll
        for (int r = 0; r < 32; ++r) {
            int i = i0 + r;
            float  w  = Ws[(i << 4) + jl];
            float4 h4 = hs[i];
            acc.x = fmaf(w, h4.x, acc.x);
            acc.y = fmaf(w, h4.y, acc.y);
            acc.z = fmaf(w, h4.z, acc.z);
            acc.w = fmaf(w, h4.w, acc.w);
        }
        *reinterpret_cast<float4*>(&red[(ic << 6) + (jl << 2)]) = acc;
        __syncthreads();

        if (tid < 64) {
            int jj = tid >> 2, b = tid & 3;
            float sum = 0.f;
            #pragma unroll
            for (int c = 0; c < 16; ++c) sum += red[(c << 6) + (jj << 2) + b];
            sum += g_X[(size_t)((b << 8) + s) * NH + j0 + jj];
            g_rnn[(size_t)((b << 8) + s) * NH + j0 + jj] = ftanh(sum);
        }
        __threadfence();
        __syncthreads();
        if (tid == 0) atomicAdd(&g_bar, 1u);
    }
}

// Generic fp32 tiled GEMM: C[M,N] = A[M,K] @ B[K,N] (+bias1) (+bias2), row-major.
template<int BM, int BN, int BK, int TM, int TN>
__global__ __launch_bounds__((BM / TM) * (BN / TN))
void gemm_kernel(const float* __restrict__ A, const float* __restrict__ B,
                 float* __restrict__ C, int M, int N, int K,
                 const float* __restrict__ bias1, const float* __restrict__ bias2) {
    __shared__ float As[2][BK][BM];
    __shared__ float Bs[2][BK][BN];
    const int tid  = threadIdx.x;
    const int arow = tid / (BK / 4);
    const int acol = (tid % (BK / 4)) * 4;
    const int brow = tid / (BN / 4);
    const int bcol = (tid % (BN / 4)) * 4;
    const float* Ap = A + (size_t)(blockIdx.y * BM + arow) * K + acol;
    const float* Bp = B + (size_t)brow * N + blockIdx.x * BN + bcol;
    const int tx = tid % (BN / TN);
    const int ty = tid / (BN / TN);

    float acc[TM][TN];
    #pragma unroll
    for (int i = 0; i < TM; ++i)
        #pragma unroll
        for (int j = 0; j < TN; ++j) acc[i][j] = 0.f;

    float4 ra = *reinterpret_cast<const float4*>(Ap);
    float4 rb = *reinterpret_cast<const float4*>(Bp);
    As[0][acol + 0][arow] = ra.x; As[0][acol + 1][arow] = ra.y;
    As[0][acol + 2][arow] = ra.z; As[0][acol + 3][arow] = ra.w;
    *reinterpret_cast<float4*>(&Bs[0][brow][bcol]) = rb;
    __syncthreads();

    const int KT = K / BK;
    for (int kt = 0; kt < KT; ++kt) {
        const int cur = kt & 1;
        if (kt + 1 < KT) {
            ra = *reinterpret_cast<const float4*>(Ap + (size_t)(kt + 1) * BK);
            rb = *reinterpret_cast<const float4*>(Bp + (size_t)(kt + 1) * BK * N);
        }
        #pragma unroll
        for (int k = 0; k < BK; ++k) {
            float a[TM], b[TN];
            #pragma unroll
            for (int u = 0; u < TM; u += 4) {
                float4 t = *reinterpret_cast<const float4*>(&As[cur][k][ty * TM + u]);
                a[u] = t.x; a[u + 1] = t.y; a[u + 2] = t.z; a[u + 3] = t.w;
            }
            #pragma unroll
            for (int u = 0; u < TN; u += 4) {
                float4 t = *reinterpret_cast<const float4*>(&Bs[cur][k][tx * TN + u]);
                b[u] = t.x; b[u + 1] = t.y; b[u + 2] = t.z; b[u + 3] = t.w;
            }
            #pragma unroll
            for (int i = 0; i < TM; ++i)
                #pragma unroll
                for (int j = 0; j < TN; ++j)
                    acc[i][j] = fmaf(a[i], b[j], acc[i][j]);
        }
        if (kt + 1 < KT) {
            const int nxt = cur ^ 1;
            As[nxt][acol + 0][arow] = ra.x; As[nxt][acol + 1][arow] = ra.y;
            As[nxt][acol + 2][arow] = ra.z; As[nxt][acol + 3][arow] = ra.w;
            *reinterpret_cast<float4*>(&Bs[nxt][brow][bcol]) = rb;
        }
        __syncthreads();
    }

    #pragma unroll
    for (int i = 0; i < TM; ++i) {
        size_t row = (size_t)blockIdx.y * BM + ty * TM + i;
        #pragma unroll
        for (int j = 0; j < TN; j += 4) {
            int col = blockIdx.x * BN + tx * TN + j;
            float4 v = make_float4(acc[i][j], acc[i][j + 1], acc[i][j + 2], acc[i][j + 3]);
            if (bias1) { v.x += bias1[col]; v.y += bias1[col+1]; v.z += bias1[col+2]; v.w += bias1[col+3]; }
            if (bias2) { v.x += bias2[col]; v.y += bias2[col+1]; v.z += bias2[col+2]; v.w += bias2[col+3]; }
            *reinterpret_cast<float4*>(&C[row * N + col]) = v;
        }
    }
}

// scores[b,d,e] = sum_h tanh(penc[b,e,h]+pdec[b,d,h]) * v[h], e <= d.  Warp per e.
__global__ __launch_bounds__(256) void scores_kernel(const float* __restrict__ attn_v) {
    __shared__ float pdec_s[NH];
    __shared__ float v_s[NH];
    const int d = blockIdx.x, b = blockIdx.y;
    const int tid = threadIdx.x, lane = tid & 31, wid = tid >> 5;

    for (int i = tid; i < NH; i += 256) {
        pdec_s[i] = g_pdec[(size_t)((b << 8) + d) * NH + i];
        v_s[i]    = attn_v[i];
    }
    __syncthreads();

    for (int e0 = 0; e0 <= d; e0 += 8) {
        int e = e0 + wid;
        if (e <= d) {
            const float* pe = g_penc + (size_t)((b << 8) + e) * NH;
            float acc = 0.f;
            #pragma unroll
            for (int q = 0; q < 4; ++q) {
                int h = (lane << 2) + (q << 7);
                float4 p = *reinterpret_cast<const float4*>(pe + h);
                float4 pd = *reinterpret_cast<const float4*>(&pdec_s[h]);
                float4 vv = *reinterpret_cast<const float4*>(&v_s[h]);
                acc = fmaf(ftanh(p.x + pd.x), vv.x, acc);
                acc = fmaf(ftanh(p.y + pd.y), vv.y, acc);
                acc = fmaf(ftanh(p.z + pd.z), vv.z, acc);
                acc = fmaf(ftanh(p.w + pd.w), vv.w, acc);
            }
            #pragma unroll
            for (int o = 16; o; o >>= 1) acc += __shfl_xor_sync(0xFFFFFFFFu, acc, o);
            if (lane == 0) g_scores[(size_t)((b << 8) + d) * NT + e] = acc;
        }
    }
}

// softmax over e<=d, context = sum_e w_e * rnn[b,e,:], write combined = [rnn_d, ctx].
__global__ __launch_bounds__(128) void softmax_ctx_kernel() {
    __shared__ float w_s[NT];
    __shared__ float sm[4];
    const int d = blockIdx.x, b = blockIdx.y, tid = threadIdx.x;
    const int n = d + 1;
    const float* srow = g_scores + (size_t)((b << 8) + d) * NT;

    float s0 = (tid < n) ? srow[tid] : -1e30f;
    float s1 = (tid + 128 < n) ? srow[tid + 128] : -1e30f;
    float m = fmaxf(s0, s1);
    #pragma unroll
    for (int o = 16; o; o >>= 1) m = fmaxf(m, __shfl_xor_sync(0xFFFFFFFFu, m, o));
    if ((tid & 31) == 0) sm[tid >> 5] = m;
    __syncthreads();
    m = fmaxf(fmaxf(sm[0], sm[1]), fmaxf(sm[2], sm[3]));
    __syncthreads();

    float e0 = (tid < n) ? fexp(s0 - m) : 0.f;
    float e1 = (tid + 128 < n) ? fexp(s1 - m) : 0.f;
    float sum = e0 + e1;
    #pragma unroll
    for (int o = 16; o; o >>= 1) sum += __shfl_xor_sync(0xFFFFFFFFu, sum, o);
    if ((tid & 31) == 0) sm[tid >> 5] = sum;
    __syncthreads();
    sum = sm[0] + sm[1] + sm[2] + sm[3];
    float inv = frcp_pos(sum);
    if (tid < n) w_s[tid] = e0 * inv;
    if (tid + 128 < n) w_s[tid + 128] = e1 * inv;
    __syncthreads();

    float4 acc = make_float4(0.f, 0.f, 0.f, 0.f);
    const float* rb = g_rnn + (size_t)(b << 8) * NH + (tid << 2);
    for (int e = 0; e < n; ++e) {
        float w = w_s[e];
        float4 r = *reinterpret_cast<const float4*>(rb + (size_t)e * NH);
        acc.x = fmaf(w, r.x, acc.x);
        acc.y = fmaf(w, r.y, acc.y);
        acc.z = fmaf(w, r.z, acc.z);
        acc.w = fmaf(w, r.w, acc.w);
    }
    float4 own = *reinterpret_cast<const float4*>(
        g_rnn + (size_t)((b << 8) + d) * NH + (tid << 2));
    float* cm = g_comb + (size_t)((b << 8) + d) * (2 * NH);
    *reinterpret_cast<float4*>(cm + (tid << 2)) = own;
    *reinterpret_cast<float4*>(cm + NH + (tid << 2)) = acc;
}

__global__ void hlast_kernel(float* __restrict__ out) {
    int idx = blockIdx.x * 512 + threadIdx.x;     // 0..2047
    int b = idx >> 9, i = idx & 511;
    out[idx] = g_rnn[(size_t)((b << 8) + (NT - 1)) * NH + i];
}

// ---------------- launch ----------------
extern "C" void kernel_launch(void* const* d_in, const int* in_sizes, int n_in,
                              void* d_out, int out_size) {
    const int*   x      = (const int*)  d_in[0];
    const float* embed  = (const float*)d_in[1];
    const float* W_ih   = (const float*)d_in[2];
    const float* W_hh   = (const float*)d_in[3];
    const float* b_ih   = (const float*)d_in[4];
    const float* b_hh   = (const float*)d_in[5];
    const float* attn_W = (const float*)d_in[6];
    const float* attn_U = (const float*)d_in[7];
    const float* attn_v = (const float*)d_in[8];
    const float* fc_W   = (const float*)d_in[9];
    const float* fc_b   = (const float*)d_in[10];
    const float* h0     = (const float*)d_in[11];
    float* out = (float*)d_out;

    float *emb, *X, *rnn, *penc, *pdec, *comb;
    cudaGetSymbolAddress((void**)&emb,  g_emb);
    cudaGetSymbolAddress((void**)&X,    g_X);
    cudaGetSymbolAddress((void**)&rnn,  g_rnn);
    cudaGetSymbolAddress((void**)&penc, g_penc);
    cudaGetSymbolAddress((void**)&pdec, g_pdec);
    cudaGetSymbolAddress((void**)&comb, g_comb);

    reset_kernel<<<1, 1>>>();
    gather_kernel<<<BT * NE / 4 / 256, 256>>>(x, embed);
    gemm_kernel<64, 64, 16, 4, 4><<<dim3(NH / 64, BT / 64), 256>>>(
        emb, W_ih, X, BT, NH, NE, b_ih, b_hh);
    rnn_kernel<<<RNN_BLOCKS, 256>>>(W_hh, h0);
    gemm_kernel<64, 64, 16, 4, 4><<<dim3(NH / 64, BT / 64), 256>>>(
        rnn, attn_W, penc, BT, NH, NH, nullptr, nullptr);
    gemm_kernel<64, 64, 16, 4, 4><<<dim3(NH / 64, BT / 64), 256>>>(
        rnn, attn_U, pdec, BT, NH, NH, nullptr, nullptr);
    scores_kernel<<<dim3(NT, NB), 256>>>(attn_v);
    softmax_ctx_kernel<<<dim3(NT, NB), 128>>>();
    gemm_kernel<128, 128, 8, 8, 8><<<dim3(NV / 128, BT / 128), 256>>>(
        comb, fc_W, out, BT, NV, 2 * NH, fc_b, nullptr);
    hlast_kernel<<<4, 512>>>(out + (size_t)BT * NV);
}

// round 6
// speedup vs baseline: 1.0057x; 1.0006x over previous
#include <cuda_runtime.h>

constexpr int NB = 4, NT = 256, NH = 512, NE = 512, NV = 32000;
constexpr int BT = NB * NT;                 // 1024
constexpr int RNN_BLOCKS = 32, RNN_JCOL = 16;

// ---------------- device scratch (no allocations allowed) ----------------
__device__ float g_emb   [BT * NE];
__device__ float g_X     [BT * NH];
__device__ float g_rnn   [BT * NH];
__device__ float g_penc  [BT * NH];
__device__ float g_pdec  [BT * NH];
__device__ float g_scores[NB * NT * NT];
__device__ float g_comb  [BT * 2 * NH];
__device__ unsigned g_bar;

// ---------------- FFMA-only math (keep off the MUFU pipe) ----------------
__device__ __forceinline__ float fexp(float x) {
    float y = x * 1.4426950408889634f;
    y = fminf(fmaxf(y, -125.f), 125.f);
    float fk = y + 12582912.f;                  // round-to-nearest via magic add
    int   k  = __float_as_int(fk) - 0x4B400000;
    float f  = y - (fk - 12582912.f);           // f in [-0.5, 0.5]
    float p  = 1.54035304e-4f;
    p = fmaf(p, f, 1.33335581e-3f);
    p = fmaf(p, f, 9.61812911e-3f);
    p = fmaf(p, f, 5.55041087e-2f);
    p = fmaf(p, f, 2.40226507e-1f);
    p = fmaf(p, f, 6.93147181e-1f);
    p = fmaf(p, f, 1.0f);
    return p * __int_as_float((k + 127) << 23);
}
__device__ __forceinline__ float frcp_pos(float d) {
    float r = __int_as_float(0x7EF311C3 - __float_as_int(d));
    r = r * (2.0f - d * r);
    r = r * (2.0f - d * r);
    r = r * (2.0f - d * r);
    return r;
}
__device__ __forceinline__ float ftanh(float x) {
    float z = fminf(fmaxf(x, -10.f), 10.f);
    float t = fexp(2.0f * z);
    return 1.0f - 2.0f * frcp_pos(t + 1.0f);
}

// ---------------- kernels ----------------
__global__ void reset_kernel() { g_bar = 0u; }

__global__ __launch_bounds__(256) void gather_kernel(const int* __restrict__ x,
                                                     const float* __restrict__ embed) {
    int idx = blockIdx.x * 256 + threadIdx.x;     // over BT*NE/4
    int m = idx >> 7, c = idx & 127;              // NE/4 = 128
    int tok = x[m];
    reinterpret_cast<float4*>(g_emb)[idx] =
        reinterpret_cast<const float4*>(embed)[(size_t)tok * (NE / 4) + c];
}

// Persistent RNN scan: 32 blocks, each owns 16 output columns.
__global__ __launch_bounds__(256) void rnn_kernel(const float* __restrict__ Whh,
                                                  const float* __restrict__ h0) {
    __shared__ float  Ws[NH * RNN_JCOL];     // 32 KB
    __shared__ float4 hs[NH];                // 8 KB (h transposed: hs[i] = batches 0..3)
    __shared__ float  red[16 * 64];          // 4 KB

    const int tid = threadIdx.x;
    const int j0  = blockIdx.x * RNN_JCOL;
    for (int idx = tid; idx < NH * RNN_JCOL; idx += 256) {
        int i = idx >> 4, jl = idx & 15;
        Ws[idx] = Whh[i * NH + j0 + jl];
    }
    const int ic = tid >> 4;      // 0..15, each handles 32 rows
    const int jl = tid & 15;
    const int i0 = ic << 5;

    for (int s = 0; s < NT; ++s) {
        if (s > 0 && tid == 0) {
            unsigned target = (unsigned)(RNN_BLOCKS * s);
            while (*((volatile unsigned*)&g_bar) < target) {}
        }
        __syncthreads();
        #pragma unroll
        for (int q = 0; q < 8; ++q) {
            int idx = (q << 8) + tid;
            int b = idx >> 9, i = idx & (NH - 1);
            float v = (s == 0) ? h0[idx]
                               : g_rnn[(size_t)(((b << 8) + (s - 1))) * NH + i];
            reinterpret_cast<float*>(hs)[(i << 2) + b] = v;
        }
        __syncthreads();

        float4 acc = make_float4(0.f, 0.f, 0.f, 0.f);
        #pragma unroll
        for (int r = 0; r < 32; ++r) {
            int i = i0 + r;
            float  w  = Ws[(i << 4) + jl];
            float4 h4 = hs[i];
            acc.x = fmaf(w, h4.x, acc.x);
            acc.y = fmaf(w, h4.y, acc.y);
            acc.z = fmaf(w, h4.z, acc.z);
            acc.w = fmaf(w, h4.w, acc.w);
        }
        *reinterpret_cast<float4*>(&red[(ic << 6) + (jl << 2)]) = acc;
        __syncthreads();

        if (tid < 64) {
            int jj = tid >> 2, b = tid & 3;
            float sum = 0.f;
            #pragma unroll
            for (int c = 0; c < 16; ++c) sum += red[(c << 6) + (jj << 2) + b];
            sum += g_X[(size_t)((b << 8) + s) * NH + j0 + jj];
            g_rnn[(size_t)((b << 8) + s) * NH + j0 + jj] = ftanh(sum);
        }
        __threadfence();
        __syncthreads();
        if (tid == 0) atomicAdd(&g_bar, 1u);
    }
}

// Generic fp32 tiled GEMM: C[M,N] = A[M,K] @ B[K,N] (+bias1) (+bias2), row-major.
template<int BM, int BN, int BK, int TM, int TN>
__global__ __launch_bounds__((BM / TM) * (BN / TN))
void gemm_kernel(const float* __restrict__ A, const float* __restrict__ B,
                 float* __restrict__ C, int M, int N, int K,
                 const float* __restrict__ bias1, const float* __restrict__ bias2) {
    __shared__ float As[2][BK][BM];
    __shared__ float Bs[2][BK][BN];
    const int tid  = threadIdx.x;
    const int arow = tid / (BK / 4);
    const int acol = (tid % (BK / 4)) * 4;
    const int brow = tid / (BN / 4);
    const int bcol = (tid % (BN / 4)) * 4;
    const float* Ap = A + (size_t)(blockIdx.y * BM + arow) * K + acol;
    const float* Bp = B + (size_t)brow * N + blockIdx.x * BN + bcol;
    const int tx = tid % (BN / TN);
    const int ty = tid / (BN / TN);

    float acc[TM][TN];
    #pragma unroll
    for (int i = 0; i < TM; ++i)
        #pragma unroll
        for (int j = 0; j < TN; ++j) acc[i][j] = 0.f;

    float4 ra = *reinterpret_cast<const float4*>(Ap);
    float4 rb = *reinterpret_cast<const float4*>(Bp);
    As[0][acol + 0][arow] = ra.x; As[0][acol + 1][arow] = ra.y;
    As[0][acol + 2][arow] = ra.z; As[0][acol + 3][arow] = ra.w;
    *reinterpret_cast<float4*>(&Bs[0][brow][bcol]) = rb;
    __syncthreads();

    const int KT = K / BK;
    for (int kt = 0; kt < KT; ++kt) {
        const int cur = kt & 1;
        if (kt + 1 < KT) {
            ra = *reinterpret_cast<const float4*>(Ap + (size_t)(kt + 1) * BK);
            rb = *reinterpret_cast<const float4*>(Bp + (size_t)(kt + 1) * BK * N);
        }
        #pragma unroll
        for (int k = 0; k < BK; ++k) {
            float a[TM], b[TN];
            #pragma unroll
            for (int u = 0; u < TM; u += 4) {
                float4 t = *reinterpret_cast<const float4*>(&As[cur][k][ty * TM + u]);
                a[u] = t.x; a[u + 1] = t.y; a[u + 2] = t.z; a[u + 3] = t.w;
            }
            #pragma unroll
            for (int u = 0; u < TN; u += 4) {
                float4 t = *reinterpret_cast<const float4*>(&Bs[cur][k][tx * TN + u]);
                b[u] = t.x; b[u + 1] = t.y; b[u + 2] = t.z; b[u + 3] = t.w;
            }
            #pragma unroll
            for (int i = 0; i < TM; ++i)
                #pragma unroll
                for (int j = 0; j < TN; ++j)
                    acc[i][j] = fmaf(a[i], b[j], acc[i][j]);
        }
        if (kt + 1 < KT) {
            const int nxt = cur ^ 1;
            As[nxt][acol + 0][arow] = ra.x; As[nxt][acol + 1][arow] = ra.y;
            As[nxt][acol + 2][arow] = ra.z; As[nxt][acol + 3][arow] = ra.w;
            *reinterpret_cast<float4*>(&Bs[nxt][brow][bcol]) = rb;
        }
        __syncthreads();
    }

    #pragma unroll
    for (int i = 0; i < TM; ++i) {
        size_t row = (size_t)blockIdx.y * BM + ty * TM + i;
        #pragma unroll
        for (int j = 0; j < TN; j += 4) {
            int col = blockIdx.x * BN + tx * TN + j;
            float4 v = make_float4(acc[i][j], acc[i][j + 1], acc[i][j + 2], acc[i][j + 3]);
            if (bias1) { v.x += bias1[col]; v.y += bias1[col+1]; v.z += bias1[col+2]; v.w += bias1[col+3]; }
            if (bias2) { v.x += bias2[col]; v.y += bias2[col+1]; v.z += bias2[col+2]; v.w += bias2[col+3]; }
            *reinterpret_cast<float4*>(&C[row * N + col]) = v;
        }
    }
}

// scores[b,d,e] = sum_h tanh(penc[b,e,h]+pdec[b,d,h]) * v[h], e <= d.  Warp per e.
__global__ __launch_bounds__(256) void scores_kernel(const float* __restrict__ attn_v) {
    __shared__ float pdec_s[NH];
    __shared__ float v_s[NH];
    const int d = blockIdx.x, b = blockIdx.y;
    const int tid = threadIdx.x, lane = tid & 31, wid = tid >> 5;

    for (int i = tid; i < NH; i += 256) {
        pdec_s[i] = g_pdec[(size_t)((b << 8) + d) * NH + i];
        v_s[i]    = attn_v[i];
    }
    __syncthreads();

    for (int e0 = 0; e0 <= d; e0 += 8) {
        int e = e0 + wid;
        if (e <= d) {
            const float* pe = g_penc + (size_t)((b << 8) + e) * NH;
            float acc = 0.f;
            #pragma unroll
            for (int q = 0; q < 4; ++q) {
                int h = (lane << 2) + (q << 7);
                float4 p = *reinterpret_cast<const float4*>(pe + h);
                float4 pd = *reinterpret_cast<const float4*>(&pdec_s[h]);
                float4 vv = *reinterpret_cast<const float4*>(&v_s[h]);
                acc = fmaf(ftanh(p.x + pd.x), vv.x, acc);
                acc = fmaf(ftanh(p.y + pd.y), vv.y, acc);
                acc = fmaf(ftanh(p.z + pd.z), vv.z, acc);
                acc = fmaf(ftanh(p.w + pd.w), vv.w, acc);
            }
            #pragma unroll
            for (int o = 16; o; o >>= 1) acc += __shfl_xor_sync(0xFFFFFFFFu, acc, o);
            if (lane == 0) g_scores[(size_t)((b << 8) + d) * NT + e] = acc;
        }
    }
}

// softmax over e<=d, context = sum_e w_e * rnn[b,e,:], write combined = [rnn_d, ctx].
__global__ __launch_bounds__(128) void softmax_ctx_kernel() {
    __shared__ float w_s[NT];
    __shared__ float sm[4];
    const int d = blockIdx.x, b = blockIdx.y, tid = threadIdx.x;
    const int n = d + 1;
    const float* srow = g_scores + (size_t)((b << 8) + d) * NT;

    float s0 = (tid < n) ? srow[tid] : -1e30f;
    float s1 = (tid + 128 < n) ? srow[tid + 128] : -1e30f;
    float m = fmaxf(s0, s1);
    #pragma unroll
    for (int o = 16; o; o >>= 1) m = fmaxf(m, __shfl_xor_sync(0xFFFFFFFFu, m, o));
    if ((tid & 31) == 0) sm[tid >> 5] = m;
    __syncthreads();
    m = fmaxf(fmaxf(sm[0], sm[1]), fmaxf(sm[2], sm[3]));
    __syncthreads();

    float e0 = (tid < n) ? fexp(s0 - m) : 0.f;
    float e1 = (tid + 128 < n) ? fexp(s1 - m) : 0.f;
    float sum = e0 + e1;
    #pragma unroll
    for (int o = 16; o; o >>= 1) sum += __shfl_xor_sync(0xFFFFFFFFu, sum, o);
    if ((tid & 31) == 0) sm[tid >> 5] = sum;
    __syncthreads();
    sum = sm[0] + sm[1] + sm[2] + sm[3];
    float inv = frcp_pos(sum);
    if (tid < n) w_s[tid] = e0 * inv;
    if (tid + 128 < n) w_s[tid + 128] = e1 * inv;
    __syncthreads();

    float4 acc = make_float4(0.f, 0.f, 0.f, 0.f);
    const float* rb = g_rnn + (size_t)(b << 8) * NH + (tid << 2);
    for (int e = 0; e < n; ++e) {
        float w = w_s[e];
        float4 r = *reinterpret_cast<const float4*>(rb + (size_t)e * NH);
        acc.x = fmaf(w, r.x, acc.x);
        acc.y = fmaf(w, r.y, acc.y);
        acc.z = fmaf(w, r.z, acc.z);
        acc.w = fmaf(w, r.w, acc.w);
    }
    float4 own = *reinterpret_cast<const float4*>(
        g_rnn + (size_t)((b << 8) + d) * NH + (tid << 2));
    float* cm = g_comb + (size_t)((b << 8) + d) * (2 * NH);
    *reinterpret_cast<float4*>(cm + (tid << 2)) = own;
    *reinterpret_cast<float4*>(cm + NH + (tid << 2)) = acc;
}

__global__ void hlast_kernel(float* __restrict__ out) {
    int idx = blockIdx.x * 512 + threadIdx.x;     // 0..2047
    int b = idx >> 9, i = idx & 511;
    out[idx] = g_rnn[(size_t)((b << 8) + (NT - 1)) * NH + i];
}

// ---------------- launch ----------------
extern "C" void kernel_launch(void* const* d_in, const int* in_sizes, int n_in,
                              void* d_out, int out_size) {
    const int*   x      = (const int*)  d_in[0];
    const float* embed  = (const float*)d_in[1];
    const float* W_ih   = (const float*)d_in[2];
    const float* W_hh   = (const float*)d_in[3];
    const float* b_ih   = (const float*)d_in[4];
    const float* b_hh   = (const float*)d_in[5];
    const float* attn_W = (const float*)d_in[6];
    const float* attn_U = (const float*)d_in[7];
    const float* attn_v = (const float*)d_in[8];
    const float* fc_W   = (const float*)d_in[9];
    const float* fc_b   = (const float*)d_in[10];
    const float* h0     = (const float*)d_in[11];
    float* out = (float*)d_out;

    float *emb, *X, *rnn, *penc, *pdec, *comb;
    cudaGetSymbolAddress((void**)&emb,  g_emb);
    cudaGetSymbolAddress((void**)&X,    g_X);
    cudaGetSymbolAddress((void**)&rnn,  g_rnn);
    cudaGetSymbolAddress((void**)&penc, g_penc);
    cudaGetSymbolAddress((void**)&pdec, g_pdec);
    cudaGetSymbolAddress((void**)&comb, g_comb);

    reset_kernel<<<1, 1>>>();
    gather_kernel<<<BT * NE / 4 / 256, 256>>>(x, embed);
    gemm_kernel<64, 64, 16, 4, 4><<<dim3(NH / 64, BT / 64), 256>>>(
        emb, W_ih, X, BT, NH, NE, b_ih, b_hh);
    rnn_kernel<<<RNN_BLOCKS, 256>>>(W_hh, h0);
    gemm_kernel<64, 64, 16, 4, 4><<<dim3(NH / 64, BT / 64), 256>>>(
        rnn, attn_W, penc, BT, NH, NH, nullptr, nullptr);
    gemm_kernel<64, 64, 16, 4, 4><<<dim3(NH / 64, BT / 64), 256>>>(
        rnn, attn_U, pdec, BT, NH, NH, nullptr, nullptr);
    scores_kernel<<<dim3(NT, NB), 256>>>(attn_v);
    softmax_ctx_kernel<<<dim3(NT, NB), 128>>>();
    gemm_kernel<128, 128, 8, 8, 8><<<dim3(NV / 128, BT / 128), 256>>>(
        comb, fc_W, out, BT, NV, 2 * NH, fc_b, nullptr);
    hlast_kernel<<<4, 512>>>(out + (size_t)BT * NV);
}